// round 3
// baseline (speedup 1.0000x reference)
#include <cuda_runtime.h>
#include <cstdint>

#define NNODES 50000
#define NEDGES 600000
#define LLMD 640
#define HID 128
#define POUT 112   // HIDDEN - STRUCT_DIM
#define SDIM 16

// ---------------- scratch (static device globals; no allocation) ----------------
__device__ float g_x[(size_t)NNODES * HID];
__device__ float g_y[(size_t)NNODES * HID];
__device__ float g_dis[NNODES];
__device__ int   g_deg[NNODES];
__device__ int   g_off[NNODES + 1];
__device__ int   g_cur[NNODES];
__device__ int   g_csr[NEDGES];
__device__ int   g_is64;

// ---------------- dtype probe: int64 vs int32 indices ----------------
// If data is int64 (values < 2^31), every odd 32-bit word is 0.
__global__ void k_probe(const int* __restrict__ e32) {
    __shared__ int s_any;
    if (threadIdx.x == 0) s_any = 0;
    __syncthreads();
    int a = 0;
    for (int i = threadIdx.x; i < 4096; i += blockDim.x) a |= e32[2 * i + 1];
    if (a) atomicOr(&s_any, 1);
    __syncthreads();
    if (threadIdx.x == 0) g_is64 = (s_any == 0) ? 1 : 0;
}

__device__ __forceinline__ int load_idx(const void* p, long long i, int is64) {
    if (is64) return (int)((const long long*)p)[i];
    return ((const int*)p)[i];
}

// ---------------- degree histogram ----------------
__global__ void k_zero_deg() {
    int i = blockIdx.x * blockDim.x + threadIdx.x;
    if (i < NNODES) g_deg[i] = 0;
}

__global__ void k_hist(const void* __restrict__ edges) {
    int e = blockIdx.x * blockDim.x + threadIdx.x;
    if (e >= NEDGES) return;
    int is64 = g_is64;
    int dst = load_idx(edges, (long long)NEDGES + e, is64);
    atomicAdd(&g_deg[dst], 1);
}

// ---------------- single-block exclusive scan (also computes dis) ----------------
__global__ void k_scan() {
    __shared__ int warp_sums[32];
    __shared__ int carry_s;
    const int t = threadIdx.x;           // 1024 threads
    const int lane = t & 31, w = t >> 5;
    if (t == 0) carry_s = 0;
    __syncthreads();
    for (int base = 0; base < NNODES; base += 1024) {
        int idx = base + t;
        int v = (idx < NNODES) ? g_deg[idx] : 0;
        if (idx < NNODES) g_dis[idx] = rsqrtf(1.0f + (float)v);
        // warp inclusive scan
        int inc = v;
        #pragma unroll
        for (int o = 1; o < 32; o <<= 1) {
            int n = __shfl_up_sync(0xFFFFFFFFu, inc, o);
            if (lane >= o) inc += n;
        }
        if (lane == 31) warp_sums[w] = inc;
        __syncthreads();
        if (t < 32) {
            int s = warp_sums[t];
            #pragma unroll
            for (int o = 1; o < 32; o <<= 1) {
                int n = __shfl_up_sync(0xFFFFFFFFu, s, o);
                if (t >= o) s += n;
            }
            warp_sums[t] = s;  // inclusive over warp totals
        }
        __syncthreads();
        int warp_prefix = (w > 0) ? warp_sums[w - 1] : 0;
        int excl = carry_s + warp_prefix + inc - v;
        if (idx < NNODES) { g_off[idx] = excl; g_cur[idx] = excl; }
        __syncthreads();
        if (t == 0) carry_s += warp_sums[31];
        __syncthreads();
    }
    if (t == 0) g_off[NNODES] = carry_s;
}

// ---------------- CSR fill ----------------
__global__ void k_fill(const void* __restrict__ edges) {
    int e = blockIdx.x * blockDim.x + threadIdx.x;
    if (e >= NEDGES) return;
    int is64 = g_is64;
    int src = load_idx(edges, e, is64);
    int dst = load_idx(edges, (long long)NEDGES + e, is64);
    int p = atomicAdd(&g_cur[dst], 1);
    g_csr[p] = src;
}

// ---------------- projection GEMM + struct-emb concat ----------------
// C[row, 0:112]  = A[row,:] @ B + bias     (A: [N,640], B: [640,112])
// C[row, 112:128] = struct_emb[tid[row], :]
__global__ __launch_bounds__(256) void k_gemm_proj(
    const float* __restrict__ A, const float* __restrict__ B,
    const float* __restrict__ bias, const void* __restrict__ tids,
    const float* __restrict__ semb)
{
    __shared__ float sA[16][68];   // [k][m], padded stride 68 (16B-aligned rows)
    __shared__ float sB[16][128];  // [k][n]
    const int tid = threadIdx.x;
    const int tx = tid & 15;       // col group
    const int ty = tid >> 4;       // row group
    const int bm = blockIdx.x * 64;

    float acc[4][8];
    #pragma unroll
    for (int i = 0; i < 4; i++)
        #pragma unroll
        for (int j = 0; j < 8; j++) acc[i][j] = 0.0f;

    const int lm = tid >> 2;          // 0..63: A-tile row
    const int lk = (tid & 3) * 4;     // A-tile k offset
    const int arow = bm + lm;
    const bool avalid = arow < NNODES;
    const float* Aptr = A + (size_t)arow * LLMD + lk;
    const int bn  = tid & 127;        // B-tile col
    const int bk0 = tid >> 7;         // B-tile starting k row (0 or 1)

    for (int k0 = 0; k0 < LLMD; k0 += 16) {
        float4 av = avalid ? *(const float4*)(Aptr + k0) : make_float4(0.f, 0.f, 0.f, 0.f);
        __syncthreads();
        sA[lk + 0][lm] = av.x; sA[lk + 1][lm] = av.y;
        sA[lk + 2][lm] = av.z; sA[lk + 3][lm] = av.w;
        #pragma unroll
        for (int kk = bk0; kk < 16; kk += 2)
            sB[kk][bn] = (bn < POUT) ? B[(size_t)(k0 + kk) * POUT + bn] : 0.0f;
        __syncthreads();
        #pragma unroll
        for (int k = 0; k < 16; k++) {
            float4 a  = *(const float4*)&sA[k][ty * 4];
            float4 b0 = *(const float4*)&sB[k][tx * 4];
            float4 b1 = *(const float4*)&sB[k][64 + tx * 4];
            float av4[4] = {a.x, a.y, a.z, a.w};
            float bv[8]  = {b0.x, b0.y, b0.z, b0.w, b1.x, b1.y, b1.z, b1.w};
            #pragma unroll
            for (int i = 0; i < 4; i++)
                #pragma unroll
                for (int j = 0; j < 8; j++)
                    acc[i][j] = fmaf(av4[i], bv[j], acc[i][j]);
        }
    }

    const int is64 = g_is64;
    const int c1 = tx * 4;
    const int c2 = 64 + tx * 4;
    #pragma unroll
    for (int i = 0; i < 4; i++) {
        int row = bm + ty * 4 + i;
        if (row >= NNODES) break;
        float* Crow = g_x + (size_t)row * HID;
        float4 o1;
        o1.x = acc[i][0] + bias[c1 + 0];
        o1.y = acc[i][1] + bias[c1 + 1];
        o1.z = acc[i][2] + bias[c1 + 2];
        o1.w = acc[i][3] + bias[c1 + 3];
        *(float4*)&Crow[c1] = o1;
        float4 o2;
        if (c2 >= POUT) {
            int st = is64 ? (int)((const long long*)tids)[row] : ((const int*)tids)[row];
            const float* se = semb + (size_t)st * SDIM + (c2 - POUT);
            o2 = make_float4(se[0], se[1], se[2], se[3]);
        } else {
            o2.x = acc[i][4] + bias[c2 + 0];
            o2.y = acc[i][5] + bias[c2 + 1];
            o2.z = acc[i][6] + bias[c2 + 2];
            o2.w = acc[i][7] + bias[c2 + 3];
        }
        *(float4*)&Crow[c2] = o2;
    }
}

// ---------------- per-layer GEMM: y = (x @ W) * dis[row] ----------------
__global__ __launch_bounds__(256) void k_gemm_layer(const float* __restrict__ W) {
    __shared__ float sA[16][68];
    __shared__ float sB[16][128];
    const int tid = threadIdx.x;
    const int tx = tid & 15;
    const int ty = tid >> 4;
    const int bm = blockIdx.x * 64;

    float acc[4][8];
    #pragma unroll
    for (int i = 0; i < 4; i++)
        #pragma unroll
        for (int j = 0; j < 8; j++) acc[i][j] = 0.0f;

    const int lm = tid >> 2;
    const int lk = (tid & 3) * 4;
    const int arow = bm + lm;
    const bool avalid = arow < NNODES;
    const float* Aptr = g_x + (size_t)arow * HID + lk;
    const int bn  = tid & 127;
    const int bk0 = tid >> 7;

    for (int k0 = 0; k0 < HID; k0 += 16) {
        float4 av = avalid ? *(const float4*)(Aptr + k0) : make_float4(0.f, 0.f, 0.f, 0.f);
        __syncthreads();
        sA[lk + 0][lm] = av.x; sA[lk + 1][lm] = av.y;
        sA[lk + 2][lm] = av.z; sA[lk + 3][lm] = av.w;
        #pragma unroll
        for (int kk = bk0; kk < 16; kk += 2)
            sB[kk][bn] = W[(size_t)(k0 + kk) * HID + bn];
        __syncthreads();
        #pragma unroll
        for (int k = 0; k < 16; k++) {
            float4 a  = *(const float4*)&sA[k][ty * 4];
            float4 b0 = *(const float4*)&sB[k][tx * 4];
            float4 b1 = *(const float4*)&sB[k][64 + tx * 4];
            float av4[4] = {a.x, a.y, a.z, a.w};
            float bv[8]  = {b0.x, b0.y, b0.z, b0.w, b1.x, b1.y, b1.z, b1.w};
            #pragma unroll
            for (int i = 0; i < 4; i++)
                #pragma unroll
                for (int j = 0; j < 8; j++)
                    acc[i][j] = fmaf(av4[i], bv[j], acc[i][j]);
        }
    }

    const int c1 = tx * 4;
    const int c2 = 64 + tx * 4;
    #pragma unroll
    for (int i = 0; i < 4; i++) {
        int row = bm + ty * 4 + i;
        if (row >= NNODES) break;
        float d = g_dis[row];
        float* Crow = g_y + (size_t)row * HID;
        float4 o1 = make_float4(acc[i][0] * d, acc[i][1] * d, acc[i][2] * d, acc[i][3] * d);
        float4 o2 = make_float4(acc[i][4] * d, acc[i][5] * d, acc[i][6] * d, acc[i][7] * d);
        *(float4*)&Crow[c1] = o1;
        *(float4*)&Crow[c2] = o2;
    }
}

// ---------------- gather + relu + residual (warp per node) ----------------
__global__ __launch_bounds__(256) void k_gather(const float* __restrict__ bias) {
    int node = (blockIdx.x * blockDim.x + threadIdx.x) >> 5;
    if (node >= NNODES) return;
    int lane = threadIdx.x & 31;
    const float4* yv = (const float4*)g_y;
    float4 s = yv[(size_t)node * 32 + lane];          // self-loop term y[node]
    int b = g_off[node], e = g_off[node + 1];
    for (int i = b; i < e; i++) {
        int src = g_csr[i];
        float4 v = yv[(size_t)src * 32 + lane];
        s.x += v.x; s.y += v.y; s.z += v.z; s.w += v.w;
    }
    float d = g_dis[node];
    int c = lane * 4;
    float4 xv = *(const float4*)&g_x[(size_t)node * HID + c];
    float4 bb = *(const float4*)&bias[c];
    float4 o;
    o.x = xv.x + fmaxf(fmaf(d, s.x, bb.x), 0.0f);
    o.y = xv.y + fmaxf(fmaf(d, s.y, bb.y), 0.0f);
    o.z = xv.z + fmaxf(fmaf(d, s.z, bb.z), 0.0f);
    o.w = xv.w + fmaxf(fmaf(d, s.w, bb.w), 0.0f);
    *(float4*)&g_x[(size_t)node * HID + c] = o;
}

// ---------------- LayerNorm (warp per row) ----------------
__global__ __launch_bounds__(256) void k_ln(const float* __restrict__ g,
                                            const float* __restrict__ b,
                                            float* __restrict__ out)
{
    int row = (blockIdx.x * blockDim.x + threadIdx.x) >> 5;
    if (row >= NNODES) return;
    int lane = threadIdx.x & 31;
    int c = lane * 4;
    float4 v = *(const float4*)&g_x[(size_t)row * HID + c];
    float s = v.x + v.y + v.z + v.w;
    #pragma unroll
    for (int o = 16; o; o >>= 1) s += __shfl_xor_sync(0xFFFFFFFFu, s, o);
    float mean = s * (1.0f / HID);
    float dx = v.x - mean, dy = v.y - mean, dz = v.z - mean, dw = v.w - mean;
    float q = dx * dx + dy * dy + dz * dz + dw * dw;
    #pragma unroll
    for (int o = 16; o; o >>= 1) q += __shfl_xor_sync(0xFFFFFFFFu, q, o);
    float inv = rsqrtf(q * (1.0f / HID) + 1e-5f);
    float4 gv = *(const float4*)&g[c];
    float4 bv = *(const float4*)&b[c];
    float4 o;
    o.x = dx * inv * gv.x + bv.x;
    o.y = dy * inv * gv.y + bv.y;
    o.z = dz * inv * gv.z + bv.z;
    o.w = dw * inv * gv.w + bv.w;
    *(float4*)&out[(size_t)row * HID + c] = o;
}

// ---------------- launch ----------------
extern "C" void kernel_launch(void* const* d_in, const int* in_sizes, int n_in,
                              void* d_out, int out_size)
{
    const float* llm   = (const float*)d_in[0];
    const void*  tids  = d_in[1];
    const void*  edges = d_in[2];
    const float* projW = (const float*)d_in[3];
    const float* projB = (const float*)d_in[4];
    const float* semb  = (const float*)d_in[5];
    const float* gcnW  = (const float*)d_in[6];
    const float* gcnB  = (const float*)d_in[7];
    const float* lng   = (const float*)d_in[8];
    const float* lnb   = (const float*)d_in[9];
    float* out = (float*)d_out;

    k_probe<<<1, 256>>>((const int*)edges);
    k_zero_deg<<<(NNODES + 255) / 256, 256>>>();
    k_hist<<<(NEDGES + 255) / 256, 256>>>(edges);
    k_scan<<<1, 1024>>>();
    k_fill<<<(NEDGES + 255) / 256, 256>>>(edges);

    k_gemm_proj<<<(NNODES + 63) / 64, 256>>>(llm, projW, projB, tids, semb);

    for (int l = 0; l < 2; l++) {
        k_gemm_layer<<<(NNODES + 63) / 64, 256>>>(gcnW + (size_t)l * HID * HID);
        k_gather<<<(NNODES * 32 + 255) / 256, 256>>>(gcnB + (size_t)l * HID);
    }

    k_ln<<<(NNODES * 32 + 255) / 256, 256>>>(lng, lnb, out);
}

// round 5
// speedup vs baseline: 1.9701x; 1.9701x over previous
#include <cuda_runtime.h>
#include <cstdint>

#define NNODES 50000
#define NEDGES 600000
#define LLMD 640
#define HID 128
#define POUT 112   // HIDDEN - STRUCT_DIM
#define SDIM 16

// ---------------- scratch (static device globals; no allocation) ----------------
__device__ float g_x[(size_t)NNODES * HID];
__device__ float g_y[(size_t)NNODES * HID];
__device__ float g_dis[NNODES];
__device__ int   g_deg[NNODES];
__device__ int   g_off[NNODES + 1];
__device__ int   g_cur[NNODES];
__device__ int   g_csr[NEDGES];
__device__ int   g_is64;
__device__ float g_Wt[(size_t)POUT * LLMD];        // proj_W transposed: [112][640]
__device__ float g_WtL[2 * HID * HID];             // gcn_W transposed:  [2][n][k]
__device__ int   g_blk[64];

// ---------------- helpers ----------------
__device__ __forceinline__ uint32_t f2tf(float x) {
    uint32_t r;
    asm("cvt.rna.tf32.f32 %0, %1;" : "=r"(r) : "f"(x));
    return r;
}
__device__ __forceinline__ float4 cvt4(float4 v) {
    float4 o;
    o.x = __uint_as_float(f2tf(v.x));
    o.y = __uint_as_float(f2tf(v.y));
    o.z = __uint_as_float(f2tf(v.z));
    o.w = __uint_as_float(f2tf(v.w));
    return o;
}
__device__ __forceinline__ void mma8(float* c, const uint32_t* a, uint32_t b0, uint32_t b1) {
    asm volatile(
        "mma.sync.aligned.m16n8k8.row.col.f32.tf32.tf32.f32 "
        "{%0,%1,%2,%3}, {%4,%5,%6,%7}, {%8,%9}, {%0,%1,%2,%3};"
        : "+f"(c[0]), "+f"(c[1]), "+f"(c[2]), "+f"(c[3])
        : "r"(a[0]), "r"(a[1]), "r"(a[2]), "r"(a[3]), "r"(b0), "r"(b1));
}

// ---------------- dtype probe: int64 vs int32 indices ----------------
__global__ void k_probe(const int* __restrict__ e32) {
    __shared__ int s_any;
    if (threadIdx.x == 0) s_any = 0;
    __syncthreads();
    int a = 0;
    for (int i = threadIdx.x; i < 4096; i += blockDim.x) a |= e32[2 * i + 1];
    if (a) atomicOr(&s_any, 1);
    __syncthreads();
    if (threadIdx.x == 0) g_is64 = (s_any == 0) ? 1 : 0;
}
__device__ __forceinline__ int load_idx(const void* p, long long i, int is64) {
    if (is64) return (int)((const long long*)p)[i];
    return ((const int*)p)[i];
}

// ---------------- graph build ----------------
__global__ void k_zero_deg() {
    int i = blockIdx.x * blockDim.x + threadIdx.x;
    if (i < NNODES) g_deg[i] = 0;
}
__global__ void k_hist(const void* __restrict__ edges) {
    int e = blockIdx.x * blockDim.x + threadIdx.x;
    if (e >= NEDGES) return;
    int is64 = g_is64;
    int dst = load_idx(edges, (long long)NEDGES + e, is64);
    atomicAdd(&g_deg[dst], 1);
}
// parallel scan: phase 1 — per-block scan (49 blocks x 1024)
__global__ void k_scan1() {
    __shared__ int wsum[32];
    const int b = blockIdx.x, t = threadIdx.x, lane = t & 31, w = t >> 5;
    int idx = b * 1024 + t;
    int v = (idx < NNODES) ? g_deg[idx] : 0;
    if (idx < NNODES) g_dis[idx] = rsqrtf(1.0f + (float)v);
    int inc = v;
    #pragma unroll
    for (int o = 1; o < 32; o <<= 1) {
        int n = __shfl_up_sync(0xFFFFFFFFu, inc, o);
        if (lane >= o) inc += n;
    }
    if (lane == 31) wsum[w] = inc;
    __syncthreads();
    if (t < 32) {
        int s = wsum[t];
        #pragma unroll
        for (int o = 1; o < 32; o <<= 1) {
            int n = __shfl_up_sync(0xFFFFFFFFu, s, o);
            if (t >= o) s += n;
        }
        wsum[t] = s;
    }
    __syncthreads();
    int excl = (w > 0 ? wsum[w - 1] : 0) + inc - v;
    if (idx < NNODES) g_off[idx] = excl;
    if (t == 0) g_blk[b] = wsum[31];
}
// phase 2 — scan block totals (1 block, 64 threads)
__global__ void k_scan2() {
    __shared__ int ws[2];
    int t = threadIdx.x, lane = t & 31, w = t >> 5;
    int v = (t < 49) ? g_blk[t] : 0;
    int inc = v;
    #pragma unroll
    for (int o = 1; o < 32; o <<= 1) {
        int n = __shfl_up_sync(0xFFFFFFFFu, inc, o);
        if (lane >= o) inc += n;
    }
    if (lane == 31) ws[w] = inc;
    __syncthreads();
    int add = (w == 1) ? ws[0] : 0;
    if (t < 49) g_blk[t] = add + inc - v;
    if (t == 63) g_off[NNODES] = ws[0] + ws[1];
}
// phase 3 — add block prefixes
__global__ void k_scan3() {
    int i = blockIdx.x * blockDim.x + threadIdx.x;
    if (i < NNODES) {
        int o = g_off[i] + g_blk[i >> 10];
        g_off[i] = o;
        g_cur[i] = o;
    }
}
__global__ void k_fill(const void* __restrict__ edges) {
    int e = blockIdx.x * blockDim.x + threadIdx.x;
    if (e >= NEDGES) return;
    int is64 = g_is64;
    int src = load_idx(edges, e, is64);
    int dst = load_idx(edges, (long long)NEDGES + e, is64);
    int p = atomicAdd(&g_cur[dst], 1);
    g_csr[p] = src;
}

// ---------------- weight transposes (B operand must be [n][k]) ----------------
__global__ void k_transW(const float* __restrict__ W) {  // [640][112] -> [112][640]
    int i = blockIdx.x * blockDim.x + threadIdx.x;
    if (i < LLMD * POUT) {
        int k = i / POUT, n = i % POUT;
        g_Wt[(size_t)n * LLMD + k] = W[i];
    }
}
__global__ void k_transWL(const float* __restrict__ W) {  // [2][128][128] -> n-major
    int i = blockIdx.x * blockDim.x + threadIdx.x;
    if (i < 2 * HID * HID) {
        int l = i / (HID * HID);
        int r = i % (HID * HID);
        int k = r / HID, n = r % HID;
        g_WtL[l * HID * HID + n * HID + k] = W[i];
    }
}

// =====================================================================
// Projection GEMM via tf32 mma.sync: C[128,112] = A_tile[128,640] @ W
// block 128x112, 8 warps in 4(M)x2(N), warp tile 32x56 (2x7 mma frags)
// SMEM rows stride 36 floats: conflict-free STS.128 staging + frag LDS
// =====================================================================
#define SA_STR 36
#define PROJ_SMEM ((2*128*SA_STR + 2*112*SA_STR + 112) * 4)
__global__ __launch_bounds__(256, 1)
void k_proj_mma(const float* __restrict__ A, const float* __restrict__ bias,
                const void* __restrict__ tids, const float* __restrict__ semb)
{
    extern __shared__ float sm[];
    float* sA = sm;                        // 2 * 128 * 36
    float* sB = sm + 2 * 128 * SA_STR;     // 2 * 112 * 36
    float* sbias = sB + 2 * 112 * SA_STR;  // 112
    const int tid = threadIdx.x, wid = tid >> 5, lane = tid & 31;
    const int bm = blockIdx.x * 128;
    const int wm = (wid >> 1) * 32, wn = (wid & 1) * 56;
    const int lr = lane >> 2, lc = lane & 3;

    if (tid < POUT) sbias[tid] = bias[tid];

    float acc[2][7][4];
    #pragma unroll
    for (int i = 0; i < 2; i++)
        #pragma unroll
        for (int j = 0; j < 7; j++)
            #pragma unroll
            for (int q = 0; q < 4; q++) acc[i][j][q] = 0.0f;

    float4 ra[4], rb[4];

    auto loadG = [&](int s) {
        #pragma unroll
        for (int i = 0; i < 4; i++) {
            int idx = tid + i * 256;            // 1024 f4 : 128 rows x 8
            int row = idx >> 3, q = idx & 7;
            int grow = bm + row;
            ra[i] = (grow < NNODES)
                ? *(const float4*)(A + (size_t)grow * LLMD + s * 32 + q * 4)
                : make_float4(0.f, 0.f, 0.f, 0.f);
        }
        #pragma unroll
        for (int i = 0; i < 4; i++) {
            int idx = tid + i * 256;            // 896 f4 : 112 rows x 8
            if (idx < 896) {
                int row = idx >> 3, q = idx & 7;
                rb[i] = *(const float4*)(g_Wt + (size_t)row * LLMD + s * 32 + q * 4);
            }
        }
    };
    auto storeS = [&](int buf) {
        float* a = sA + buf * 128 * SA_STR;
        float* b = sB + buf * 112 * SA_STR;
        #pragma unroll
        for (int i = 0; i < 4; i++) {
            int idx = tid + i * 256;
            int row = idx >> 3, q = idx & 7;
            *(float4*)&a[row * SA_STR + q * 4] = cvt4(ra[i]);
        }
        #pragma unroll
        for (int i = 0; i < 4; i++) {
            int idx = tid + i * 256;
            if (idx < 896) {
                int row = idx >> 3, q = idx & 7;
                *(float4*)&b[row * SA_STR + q * 4] = cvt4(rb[i]);
            }
        }
    };
    auto compute = [&](int buf) {
        const float* a = sA + buf * 128 * SA_STR;
        const float* b = sB + buf * 112 * SA_STR;
        #pragma unroll
        for (int kk = 0; kk < 4; kk++) {
            const int k0 = kk * 8;
            uint32_t af[2][4];
            #pragma unroll
            for (int mf = 0; mf < 2; mf++) {
                const float* ap = a + (wm + mf * 16 + lr) * SA_STR + k0 + lc;
                af[mf][0] = __float_as_uint(ap[0]);
                af[mf][1] = __float_as_uint(ap[8 * SA_STR]);
                af[mf][2] = __float_as_uint(ap[4]);
                af[mf][3] = __float_as_uint(ap[8 * SA_STR + 4]);
            }
            #pragma unroll
            for (int nf = 0; nf < 7; nf++) {
                const float* bp = b + (wn + nf * 8 + lr) * SA_STR + k0 + lc;
                uint32_t b0 = __float_as_uint(bp[0]);
                uint32_t b1 = __float_as_uint(bp[4]);
                mma8(acc[0][nf], af[0], b0, b1);
                mma8(acc[1][nf], af[1], b0, b1);
            }
        }
    };

    loadG(0);
    storeS(0);
    for (int s = 0; s < 20; s++) {
        __syncthreads();
        if (s < 19) loadG(s + 1);
        compute(s & 1);
        if (s < 19) storeS((s + 1) & 1);
    }

    // epilogue: bias add + store C (cols 0..111)
    #pragma unroll
    for (int mf = 0; mf < 2; mf++) {
        int row0 = bm + wm + mf * 16 + lr;
        #pragma unroll
        for (int nf = 0; nf < 7; nf++) {
            int col = wn + nf * 8 + 2 * lc;
            float bx = sbias[col], by = sbias[col + 1];
            if (row0 < NNODES) {
                float2 v = make_float2(acc[mf][nf][0] + bx, acc[mf][nf][1] + by);
                *(float2*)&g_x[(size_t)row0 * HID + col] = v;
            }
            if (row0 + 8 < NNODES) {
                float2 v = make_float2(acc[mf][nf][2] + bx, acc[mf][nf][3] + by);
                *(float2*)&g_x[(size_t)(row0 + 8) * HID + col] = v;
            }
        }
    }
    // struct-emb concat (cols 112..127)
    const int is64 = g_is64;
    #pragma unroll
    for (int i = 0; i < 2; i++) {
        int idx = tid + i * 256;       // 512 f4 : 128 rows x 4
        int row = idx >> 2, q = idx & 3;
        int grow = bm + row;
        if (grow < NNODES) {
            int st = is64 ? (int)((const long long*)tids)[grow] : ((const int*)tids)[grow];
            float4 se = *(const float4*)(semb + (size_t)st * SDIM + q * 4);
            *(float4*)&g_x[(size_t)grow * HID + POUT + q * 4] = se;
        }
    }
}

// =====================================================================
// GCN layer GEMM via tf32 mma.sync: y[128,128] = dis[row]*(x_tile @ W)
// block 128x128, 8 warps in 4(M)x2(N), warp tile 32x64 (2x8 mma frags)
// =====================================================================
#define LAYER_SMEM ((2*128*SA_STR + 2*128*SA_STR + 128) * 4)
__global__ __launch_bounds__(256, 1)
void k_layer_mma(int l)
{
    extern __shared__ float sm[];
    float* sA = sm;
    float* sB = sm + 2 * 128 * SA_STR;
    float* sdis = sB + 2 * 128 * SA_STR;
    const int tid = threadIdx.x, wid = tid >> 5, lane = tid & 31;
    const int bm = blockIdx.x * 128;
    const int wm = (wid >> 1) * 32, wn = (wid & 1) * 64;
    const int lr = lane >> 2, lc = lane & 3;
    const float* __restrict__ Bt = g_WtL + l * HID * HID;

    if (tid < 128) sdis[tid] = (bm + tid < NNODES) ? g_dis[bm + tid] : 0.0f;

    float acc[2][8][4];
    #pragma unroll
    for (int i = 0; i < 2; i++)
        #pragma unroll
        for (int j = 0; j < 8; j++)
            #pragma unroll
            for (int q = 0; q < 4; q++) acc[i][j][q] = 0.0f;

    float4 ra[4], rb[4];

    auto loadG = [&](int s) {
        #pragma unroll
        for (int i = 0; i < 4; i++) {
            int idx = tid + i * 256;
            int row = idx >> 3, q = idx & 7;
            int grow = bm + row;
            ra[i] = (grow < NNODES)
                ? *(const float4*)(g_x + (size_t)grow * HID + s * 32 + q * 4)
                : make_float4(0.f, 0.f, 0.f, 0.f);
        }
        #pragma unroll
        for (int i = 0; i < 4; i++) {
            int idx = tid + i * 256;
            int row = idx >> 3, q = idx & 7;
            rb[i] = *(const float4*)(Bt + (size_t)row * HID + s * 32 + q * 4);
        }
    };
    auto storeS = [&](int buf) {
        float* a = sA + buf * 128 * SA_STR;
        float* b = sB + buf * 128 * SA_STR;
        #pragma unroll
        for (int i = 0; i < 4; i++) {
            int idx = tid + i * 256;
            int row = idx >> 3, q = idx & 7;
            *(float4*)&a[row * SA_STR + q * 4] = cvt4(ra[i]);
        }
        #pragma unroll
        for (int i = 0; i < 4; i++) {
            int idx = tid + i * 256;
            int row = idx >> 3, q = idx & 7;
            *(float4*)&b[row * SA_STR + q * 4] = cvt4(rb[i]);
        }
    };
    auto compute = [&](int buf) {
        const float* a = sA + buf * 128 * SA_STR;
        const float* b = sB + buf * 128 * SA_STR;
        #pragma unroll
        for (int kk = 0; kk < 4; kk++) {
            const int k0 = kk * 8;
            uint32_t af[2][4];
            #pragma unroll
            for (int mf = 0; mf < 2; mf++) {
                const float* ap = a + (wm + mf * 16 + lr) * SA_STR + k0 + lc;
                af[mf][0] = __float_as_uint(ap[0]);
                af[mf][1] = __float_as_uint(ap[8 * SA_STR]);
                af[mf][2] = __float_as_uint(ap[4]);
                af[mf][3] = __float_as_uint(ap[8 * SA_STR + 4]);
            }
            #pragma unroll
            for (int nf = 0; nf < 8; nf++) {
                const float* bp = b + (wn + nf * 8 + lr) * SA_STR + k0 + lc;
                uint32_t b0 = __float_as_uint(bp[0]);
                uint32_t b1 = __float_as_uint(bp[4]);
                mma8(acc[0][nf], af[0], b0, b1);
                mma8(acc[1][nf], af[1], b0, b1);
            }
        }
    };

    loadG(0);
    storeS(0);
    for (int s = 0; s < 4; s++) {
        __syncthreads();
        if (s < 3) loadG(s + 1);
        compute(s & 1);
        if (s < 3) storeS((s + 1) & 1);
    }

    // epilogue: y = acc * dis[row]
    #pragma unroll
    for (int mf = 0; mf < 2; mf++) {
        int rloc = wm + mf * 16 + lr;
        int row0 = bm + rloc;
        float d0 = sdis[rloc], d8 = sdis[rloc + 8];
        #pragma unroll
        for (int nf = 0; nf < 8; nf++) {
            int col = wn + nf * 8 + 2 * lc;
            if (row0 < NNODES) {
                float2 v = make_float2(acc[mf][nf][0] * d0, acc[mf][nf][1] * d0);
                *(float2*)&g_y[(size_t)row0 * HID + col] = v;
            }
            if (row0 + 8 < NNODES) {
                float2 v = make_float2(acc[mf][nf][2] * d8, acc[mf][nf][3] * d8);
                *(float2*)&g_y[(size_t)(row0 + 8) * HID + col] = v;
            }
        }
    }
}

// ---------------- gather + relu + residual (warp per node) ----------------
__global__ __launch_bounds__(256) void k_gather(const float* __restrict__ bias) {
    int node = (blockIdx.x * blockDim.x + threadIdx.x) >> 5;
    if (node >= NNODES) return;
    int lane = threadIdx.x & 31;
    const float4* yv = (const float4*)g_y;
    float4 s = yv[(size_t)node * 32 + lane];          // self-loop term y[node]
    int b = g_off[node], e = g_off[node + 1];
    for (int i = b; i < e; i++) {
        int src = g_csr[i];
        float4 v = yv[(size_t)src * 32 + lane];
        s.x += v.x; s.y += v.y; s.z += v.z; s.w += v.w;
    }
    float d = g_dis[node];
    int c = lane * 4;
    float4 xv = *(const float4*)&g_x[(size_t)node * HID + c];
    float4 bb = *(const float4*)&bias[c];
    float4 o;
    o.x = xv.x + fmaxf(fmaf(d, s.x, bb.x), 0.0f);
    o.y = xv.y + fmaxf(fmaf(d, s.y, bb.y), 0.0f);
    o.z = xv.z + fmaxf(fmaf(d, s.z, bb.z), 0.0f);
    o.w = xv.w + fmaxf(fmaf(d, s.w, bb.w), 0.0f);
    *(float4*)&g_x[(size_t)node * HID + c] = o;
}

// ---------------- LayerNorm (warp per row) ----------------
__global__ __launch_bounds__(256) void k_ln(const float* __restrict__ g,
                                            const float* __restrict__ b,
                                            float* __restrict__ out)
{
    int row = (blockIdx.x * blockDim.x + threadIdx.x) >> 5;
    if (row >= NNODES) return;
    int lane = threadIdx.x & 31;
    int c = lane * 4;
    float4 v = *(const float4*)&g_x[(size_t)row * HID + c];
    float s = v.x + v.y + v.z + v.w;
    #pragma unroll
    for (int o = 16; o; o >>= 1) s += __shfl_xor_sync(0xFFFFFFFFu, s, o);
    float mean = s * (1.0f / HID);
    float dx = v.x - mean, dy = v.y - mean, dz = v.z - mean, dw = v.w - mean;
    float q = dx * dx + dy * dy + dz * dz + dw * dw;
    #pragma unroll
    for (int o = 16; o; o >>= 1) q += __shfl_xor_sync(0xFFFFFFFFu, q, o);
    float inv = rsqrtf(q * (1.0f / HID) + 1e-5f);
    float4 gv = *(const float4*)&g[c];
    float4 bv = *(const float4*)&b[c];
    float4 o;
    o.x = dx * inv * gv.x + bv.x;
    o.y = dy * inv * gv.y + bv.y;
    o.z = dz * inv * gv.z + bv.z;
    o.w = dw * inv * gv.w + bv.w;
    *(float4*)&out[(size_t)row * HID + c] = o;
}

// ---------------- launch ----------------
extern "C" void kernel_launch(void* const* d_in, const int* in_sizes, int n_in,
                              void* d_out, int out_size)
{
    const float* llm   = (const float*)d_in[0];
    const void*  tids  = d_in[1];
    const void*  edges = d_in[2];
    const float* projW = (const float*)d_in[3];
    const float* projB = (const float*)d_in[4];
    const float* semb  = (const float*)d_in[5];
    const float* gcnW  = (const float*)d_in[6];
    const float* gcnB  = (const float*)d_in[7];
    const float* lng   = (const float*)d_in[8];
    const float* lnb   = (const float*)d_in[9];
    float* out = (float*)d_out;

    static int configured = 0;
    if (!configured) {
        cudaFuncSetAttribute(k_proj_mma,  cudaFuncAttributeMaxDynamicSharedMemorySize, PROJ_SMEM);
        cudaFuncSetAttribute(k_layer_mma, cudaFuncAttributeMaxDynamicSharedMemorySize, LAYER_SMEM);
        configured = 1;
    }

    k_probe<<<1, 256>>>((const int*)edges);
    k_zero_deg<<<(NNODES + 255) / 256, 256>>>();
    k_hist<<<(NEDGES + 255) / 256, 256>>>(edges);
    k_scan1<<<49, 1024>>>();
    k_scan2<<<1, 64>>>();
    k_scan3<<<(NNODES + 255) / 256, 256>>>();
    k_fill<<<(NEDGES + 255) / 256, 256>>>(edges);

    k_transW<<<(LLMD * POUT + 255) / 256, 256>>>(projW);
    k_transWL<<<(2 * HID * HID + 255) / 256, 256>>>(gcnW);

    const int NTILES = (NNODES + 127) / 128;  // 391
    k_proj_mma<<<NTILES, 256, PROJ_SMEM>>>(llm, projB, tids, semb);

    for (int l = 0; l < 2; l++) {
        k_layer_mma<<<NTILES, 256, LAYER_SMEM>>>(l);
        k_gather<<<(NNODES * 32 + 255) / 256, 256>>>(gcnB + (size_t)l * HID);
    }

    k_ln<<<(NNODES * 32 + 255) / 256, 256>>>(lng, lnb, out);
}